// round 1
// baseline (speedup 1.0000x reference)
#include <cuda_runtime.h>

// Problem: PBC neighbor-list distances.
// Output layout (float32): [ d2[P] | mask_c0[P] | mask_c1[P] | ... ]
//   P = N*(N-1)/2 + S*N*N
// Masks are written as 0.0f / 1.0f (reference int32 promoted on concat).

#define MAXC 4

// ---------------------------------------------------------------------------
// In-cell upper-triangle pairs: block per row i, j in (i, n).
// Row i base offset: off_i = i*(n-1) - i*(i-1)/2
// ---------------------------------------------------------------------------
__global__ void tri_kernel(const float* __restrict__ pos,
                           const float* __restrict__ cutoffs,
                           int n, int C, long long P,
                           float* __restrict__ out)
{
    int i = blockIdx.x;
    float pix = pos[3 * i + 0];
    float piy = pos[3 * i + 1];
    float piz = pos[3 * i + 2];

    float c2[MAXC];
#pragma unroll
    for (int c = 0; c < MAXC; c++) {
        if (c < C) { float cv = cutoffs[c]; c2[c] = cv * cv; }
        else c2[c] = 0.0f;
    }

    long long off = (long long)i * (n - 1) - (long long)i * (i - 1) / 2;

    for (int j = i + 1 + threadIdx.x; j < n; j += blockDim.x) {
        float dx = pix - pos[3 * j + 0];
        float dy = piy - pos[3 * j + 1];
        float dz = piz - pos[3 * j + 2];
        float d2 = dx * dx + dy * dy + dz * dz;
        long long p = off + (long long)(j - i - 1);
        out[p] = d2;
#pragma unroll
        for (int c = 0; c < MAXC; c++) {
            if (c < C)
                out[P + (long long)c * P + p] = (d2 < c2[c]) ? 1.0f : 0.0f;
        }
    }
}

// ---------------------------------------------------------------------------
// Shifted-image pairs: block per (i, s). Each thread handles 4 consecutive j
// and emits float4 stores (d2 + one mask vector per cutoff).
// Index of pair (s,i,j) = Pc + s*N*N + i*N + j.
// Pc (=499500), N (=1000), P are all divisible by 4 -> 16B-aligned stores.
// ---------------------------------------------------------------------------
__global__ void shift_kernel(const float* __restrict__ pos,
                             const float* __restrict__ cell,
                             const float* __restrict__ shifts,
                             const float* __restrict__ cutoffs,
                             int n, int C, long long Pc, long long P,
                             float* __restrict__ out)
{
    int i = blockIdx.x;
    int s = blockIdx.y;

    // shift_values[s] = shifts[s] @ cell
    float s0 = shifts[3 * s + 0], s1 = shifts[3 * s + 1], s2 = shifts[3 * s + 2];
    float svx = s0 * cell[0] + s1 * cell[3] + s2 * cell[6];
    float svy = s0 * cell[1] + s1 * cell[4] + s2 * cell[7];
    float svz = s0 * cell[2] + s1 * cell[5] + s2 * cell[8];

    float pix = pos[3 * i + 0];
    float piy = pos[3 * i + 1];
    float piz = pos[3 * i + 2];

    float c2[MAXC];
#pragma unroll
    for (int c = 0; c < MAXC; c++) {
        if (c < C) { float cv = cutoffs[c]; c2[c] = cv * cv; }
        else c2[c] = 0.0f;
    }

    long long rowbase = Pc + (long long)s * n * n + (long long)i * n;

    const float4* __restrict__ pos4 = (const float4*)pos;
    int nq = n >> 2;  // groups of 4 atoms

    for (int q = threadIdx.x; q < nq; q += blockDim.x) {
        // 12 floats = positions of atoms 4q .. 4q+3 (16B-aligned: 48*q bytes)
        float4 a = pos4[3 * q + 0];
        float4 b = pos4[3 * q + 1];
        float4 cc = pos4[3 * q + 2];

        float dx, dy, dz;
        float4 dv;
        // match reference rounding: (pi - pj) + sv
        dx = (pix - a.x) + svx;  dy = (piy - a.y) + svy;  dz = (piz - a.z) + svz;
        dv.x = dx * dx + dy * dy + dz * dz;
        dx = (pix - a.w) + svx;  dy = (piy - b.x) + svy;  dz = (piz - b.y) + svz;
        dv.y = dx * dx + dy * dy + dz * dz;
        dx = (pix - b.z) + svx;  dy = (piy - b.w) + svy;  dz = (piz - cc.x) + svz;
        dv.z = dx * dx + dy * dy + dz * dz;
        dx = (pix - cc.y) + svx; dy = (piy - cc.z) + svy; dz = (piz - cc.w) + svz;
        dv.w = dx * dx + dy * dy + dz * dz;

        ((float4*)(out + rowbase))[q] = dv;

#pragma unroll
        for (int c = 0; c < MAXC; c++) {
            if (c < C) {
                float4 mv;
                mv.x = (dv.x < c2[c]) ? 1.0f : 0.0f;
                mv.y = (dv.y < c2[c]) ? 1.0f : 0.0f;
                mv.z = (dv.z < c2[c]) ? 1.0f : 0.0f;
                mv.w = (dv.w < c2[c]) ? 1.0f : 0.0f;
                ((float4*)(out + P + (long long)c * P + rowbase))[q] = mv;
            }
        }
    }

    // scalar remainder if n % 4 != 0 (not hit for n=1000, kept for generality)
    for (int j = (nq << 2) + threadIdx.x; j < n; j += blockDim.x) {
        float dx = (pix - pos[3 * j + 0]) + svx;
        float dy = (piy - pos[3 * j + 1]) + svy;
        float dz = (piz - pos[3 * j + 2]) + svz;
        float d2 = dx * dx + dy * dy + dz * dz;
        out[rowbase + j] = d2;
#pragma unroll
        for (int c = 0; c < MAXC; c++) {
            if (c < C)
                out[P + (long long)c * P + rowbase + j] = (d2 < c2[c]) ? 1.0f : 0.0f;
        }
    }
}

extern "C" void kernel_launch(void* const* d_in, const int* in_sizes, int n_in,
                              void* d_out, int out_size)
{
    const float* pos     = (const float*)d_in[0];  // [N,3]
    const float* cell    = (const float*)d_in[1];  // [3,3]
    const float* shifts  = (const float*)d_in[2];  // [S,3]
    const float* cutoffs = (const float*)d_in[3];  // [C]

    int n = in_sizes[0] / 3;
    int S = in_sizes[2] / 3;
    int C = in_sizes[3];
    if (C > MAXC) C = MAXC;

    long long Pc = (long long)n * (n - 1) / 2;
    long long P  = Pc + (long long)S * n * n;

    float* out = (float*)d_out;

    tri_kernel<<<n, 256>>>(pos, cutoffs, n, C, P, out);

    dim3 grid(n, S);
    shift_kernel<<<grid, 256>>>(pos, cell, shifts, cutoffs, n, C, Pc, P, out);
}

// round 2
// speedup vs baseline: 1.0809x; 1.0809x over previous
#include <cuda_runtime.h>

// PBC neighbor-list distances, fused single-launch version.
// Output (float32): [ d2[P] | mask_c0[P] | mask_c1[P] | ... ]
//   P = N*(N-1)/2 + S*N*N
// gridDim = (N, S+1): y < S -> shifted-image rows; y == S -> triangle pairs.
// All element offsets fit in int32 (3P ~ 40.5M).

#define MAXC 4

__device__ __forceinline__ int tri_off(int i, int n) {
    // start offset of row i in packed upper triangle (j > i)
    return i * (2 * n - i - 1) / 2;
}

__global__ void fused_kernel(const float* __restrict__ pos,
                             const float* __restrict__ cell,
                             const float* __restrict__ shifts,
                             const float* __restrict__ cutoffs,
                             int n, int S, int C, int Pc, int P,
                             float* __restrict__ out)
{
    int i = blockIdx.x;
    int s = blockIdx.y;

    float c2[MAXC];
#pragma unroll
    for (int c = 0; c < MAXC; c++) {
        if (c < C) { float cv = cutoffs[c]; c2[c] = cv * cv; }
        else c2[c] = 0.0f;
    }

    if (s < S) {
        // ------------------- shifted-image rows -------------------
        float s0 = shifts[3 * s + 0], s1 = shifts[3 * s + 1], s2 = shifts[3 * s + 2];
        float svx = s0 * cell[0] + s1 * cell[3] + s2 * cell[6];
        float svy = s0 * cell[1] + s1 * cell[4] + s2 * cell[7];
        float svz = s0 * cell[2] + s1 * cell[5] + s2 * cell[8];

        float pix = pos[3 * i + 0];
        float piy = pos[3 * i + 1];
        float piz = pos[3 * i + 2];

        int rowbase = Pc + (s * n + i) * n;   // fits in int (max ~13.5M)

        const float4* __restrict__ pos4 = (const float4*)pos;
        int nq = n >> 2;

        for (int q = threadIdx.x; q < nq; q += blockDim.x) {
            float4 a  = pos4[3 * q + 0];
            float4 b  = pos4[3 * q + 1];
            float4 cc = pos4[3 * q + 2];

            float dx, dy, dz;
            float4 dv;
            dx = (pix - a.x) + svx;  dy = (piy - a.y) + svy;  dz = (piz - a.z) + svz;
            dv.x = dx * dx + dy * dy + dz * dz;
            dx = (pix - a.w) + svx;  dy = (piy - b.x) + svy;  dz = (piz - b.y) + svz;
            dv.y = dx * dx + dy * dy + dz * dz;
            dx = (pix - b.z) + svx;  dy = (piy - b.w) + svy;  dz = (piz - cc.x) + svz;
            dv.z = dx * dx + dy * dy + dz * dz;
            dx = (pix - cc.y) + svx; dy = (piy - cc.z) + svy; dz = (piz - cc.w) + svz;
            dv.w = dx * dx + dy * dy + dz * dz;

            *(float4*)(out + rowbase + 4 * q) = dv;

#pragma unroll
            for (int c = 0; c < MAXC; c++) {
                if (c < C) {
                    float4 mv;
                    mv.x = (dv.x < c2[c]) ? 1.0f : 0.0f;
                    mv.y = (dv.y < c2[c]) ? 1.0f : 0.0f;
                    mv.z = (dv.z < c2[c]) ? 1.0f : 0.0f;
                    mv.w = (dv.w < c2[c]) ? 1.0f : 0.0f;
                    *(float4*)(out + P + c * P + rowbase + 4 * q) = mv;
                }
            }
        }

        // scalar remainder (n % 4 != 0; not hit for n=1000)
        for (int j = (nq << 2) + threadIdx.x; j < n; j += blockDim.x) {
            float dx = (pix - pos[3 * j + 0]) + svx;
            float dy = (piy - pos[3 * j + 1]) + svy;
            float dz = (piz - pos[3 * j + 2]) + svz;
            float d2 = dx * dx + dy * dy + dz * dz;
            out[rowbase + j] = d2;
#pragma unroll
            for (int c = 0; c < MAXC; c++) {
                if (c < C)
                    out[P + c * P + rowbase + j] = (d2 < c2[c]) ? 1.0f : 0.0f;
            }
        }
    } else {
        // ------------------- in-cell triangle pairs -------------------
        // Flat pair index p in [0, Pc). Each thread handles a float4 quad.
        int Q = Pc >> 2;                          // vectorizable quads
        int t = i * blockDim.x + threadIdx.x;     // global thread id in slice

        if (t < Q) {
            int p0 = t << 2;
            // invert p -> row index via closed form, then fix up
            float nf = (float)n - 0.5f;
            float disc = nf * nf - 2.0f * (float)p0;
            int ii = (int)(nf - sqrtf(fmaxf(disc, 0.0f)));
            if (ii < 0) ii = 0;
            if (ii > n - 2) ii = n - 2;
            while (ii > 0 && tri_off(ii, n) > p0) ii--;
            while (ii < n - 2 && tri_off(ii + 1, n) <= p0) ii++;

            float4 dv;
            float* dvp = (float*)&dv;
            int row_end = tri_off(ii + 1, n);
            int jj = ii + 1 + (p0 - tri_off(ii, n));
            float pix = pos[3 * ii + 0], piy = pos[3 * ii + 1], piz = pos[3 * ii + 2];

#pragma unroll
            for (int e = 0; e < 4; e++) {
                int p = p0 + e;
                if (p >= row_end) {               // advance to next row(s)
                    do { ii++; row_end = tri_off(ii + 1, n); } while (p >= row_end);
                    jj = ii + 1 + (p - tri_off(ii, n));
                    pix = pos[3 * ii + 0]; piy = pos[3 * ii + 1]; piz = pos[3 * ii + 2];
                }
                float dx = pix - pos[3 * jj + 0];
                float dy = piy - pos[3 * jj + 1];
                float dz = piz - pos[3 * jj + 2];
                dvp[e] = dx * dx + dy * dy + dz * dz;
                jj++;
            }

            *(float4*)(out + p0) = dv;
#pragma unroll
            for (int c = 0; c < MAXC; c++) {
                if (c < C) {
                    float4 mv;
                    mv.x = (dv.x < c2[c]) ? 1.0f : 0.0f;
                    mv.y = (dv.y < c2[c]) ? 1.0f : 0.0f;
                    mv.z = (dv.z < c2[c]) ? 1.0f : 0.0f;
                    mv.w = (dv.w < c2[c]) ? 1.0f : 0.0f;
                    *(float4*)(out + P + c * P + p0) = mv;
                }
            }
        }

        // scalar tail for Pc % 4 (not hit for n=1000; handled by slice block 0)
        if (i == 0) {
            for (int p = (Q << 2) + threadIdx.x; p < Pc; p += blockDim.x) {
                float nf = (float)n - 0.5f;
                float disc = nf * nf - 2.0f * (float)p;
                int ii = (int)(nf - sqrtf(fmaxf(disc, 0.0f)));
                if (ii < 0) ii = 0;
                if (ii > n - 2) ii = n - 2;
                while (ii > 0 && tri_off(ii, n) > p) ii--;
                while (ii < n - 2 && tri_off(ii + 1, n) <= p) ii++;
                int jj = ii + 1 + (p - tri_off(ii, n));
                float dx = pos[3 * ii + 0] - pos[3 * jj + 0];
                float dy = pos[3 * ii + 1] - pos[3 * jj + 1];
                float dz = pos[3 * ii + 2] - pos[3 * jj + 2];
                float d2 = dx * dx + dy * dy + dz * dz;
                out[p] = d2;
#pragma unroll
                for (int c = 0; c < MAXC; c++) {
                    if (c < C)
                        out[P + c * P + p] = (d2 < c2[c]) ? 1.0f : 0.0f;
                }
            }
        }
    }
}

extern "C" void kernel_launch(void* const* d_in, const int* in_sizes, int n_in,
                              void* d_out, int out_size)
{
    const float* pos     = (const float*)d_in[0];  // [N,3]
    const float* cell    = (const float*)d_in[1];  // [3,3]
    const float* shifts  = (const float*)d_in[2];  // [S,3]
    const float* cutoffs = (const float*)d_in[3];  // [C]

    int n = in_sizes[0] / 3;
    int S = in_sizes[2] / 3;
    int C = in_sizes[3];
    if (C > MAXC) C = MAXC;

    int Pc = n * (n - 1) / 2;
    int P  = Pc + S * n * n;

    dim3 grid(n, S + 1);
    fused_kernel<<<grid, 256>>>(pos, cell, shifts, cutoffs, n, S, C, Pc, P,
                                (float*)d_out);
}